// round 16
// baseline (speedup 1.0000x reference)
#include <cuda_runtime.h>
#include <cstdint>

#define BB 2
#define NN 256
#define FF 64
#define HH 64
#define KK 50
#define CC 256

// ---------------- device scratch ----------------
__device__ float g_A [BB*NN*KK];
__device__ float g_Bb[BB*NN*KK];
__device__ float g_U [BB*NN*HH];
__device__ float g_Wp[BB*NN*HH];
__device__ float g_he  [BB*NN*NN*FF];
__device__ float g_attG[BB*NN*NN*4];
__device__ float g_xdnG[BB*NN*NN*4];
__device__ float g_cmp [BB*NN*2*3*CC];
__device__ float g_heE [BB*NN*2*CC];
__device__ int   g_cnt [BB*NN];

typedef unsigned long long ull;

// ---------------- helpers ----------------
__device__ __forceinline__ uint32_t smem_u32(const void* p) {
    uint32_t a;
    asm("{ .reg .u64 t; cvta.to.shared.u64 t, %1; cvt.u32.u64 %0, t; }" : "=r"(a) : "l"(p));
    return a;
}
__device__ __forceinline__ float siluf(float a) { return a * __fdividef(1.f, 1.f + __expf(-a)); }
__device__ __forceinline__ float sigm(float a)  { return __fdividef(1.f, 1.f + __expf(-a)); }
__device__ __forceinline__ float ftanh(float x) {
    float e = __expf(-2.f * fabsf(x));
    return copysignf(__fdividef(1.f - e, 1.f + e), x);
}
__device__ __forceinline__ void fma2(ull& acc, ull a, ull b) {
    asm("fma.rn.f32x2 %0, %1, %2, %0;" : "+l"(acc) : "l"(a), "l"(b));
}
__device__ __forceinline__ ull bcast2(float w) {
    ull r; asm("mov.b64 %0, {%1, %1};" : "=l"(r) : "f"(w)); return r;
}
__device__ __forceinline__ ull pack2(float a, float b) {
    ull r; asm("mov.b64 %0, {%1, %2};" : "=l"(r) : "f"(a), "f"(b)); return r;
}
__device__ __forceinline__ void unpack2(ull v, float& x, float& y) {
    asm("mov.b64 {%0, %1}, %2;" : "=f"(x), "=f"(y) : "l"(v));
}
__device__ __forceinline__ void cp16(uint32_t dst, const void* src) {
    asm volatile("cp.async.cg.shared.global [%0], [%1], 16;" :: "r"(dst), "l"(src) : "memory");
}
#define CP_COMMIT() asm volatile("cp.async.commit_group;" ::: "memory")
#define CP_WAIT0()  asm volatile("cp.async.wait_group 0;" ::: "memory")

// block reduce of 4 floats (8 warps / 256 threads). red >= 36 floats, 16B aligned.
template<int DO_MAX>
__device__ __forceinline__ float4 block_red4(float4 v, int tid, float* red) {
    #pragma unroll
    for (int o = 16; o > 0; o >>= 1) {
        float ax = __shfl_xor_sync(~0u, v.x, o), ay = __shfl_xor_sync(~0u, v.y, o);
        float az = __shfl_xor_sync(~0u, v.z, o), aw = __shfl_xor_sync(~0u, v.w, o);
        if (DO_MAX) { v.x = fmaxf(v.x, ax); v.y = fmaxf(v.y, ay); v.z = fmaxf(v.z, az); v.w = fmaxf(v.w, aw); }
        else        { v.x += ax; v.y += ay; v.z += az; v.w += aw; }
    }
    if ((tid & 31) == 0) ((float4*)red)[tid >> 5] = v;
    __syncthreads();
    if (tid < 32) {
        float4 r;
        if (tid < 8) r = ((float4*)red)[tid];
        else { float id = DO_MAX ? __int_as_float(0xff800000) : 0.f; r = make_float4(id, id, id, id); }
        #pragma unroll
        for (int o = 4; o > 0; o >>= 1) {
            float ax = __shfl_xor_sync(~0u, r.x, o), ay = __shfl_xor_sync(~0u, r.y, o);
            float az = __shfl_xor_sync(~0u, r.z, o), aw = __shfl_xor_sync(~0u, r.w, o);
            if (DO_MAX) { r.x = fmaxf(r.x, ax); r.y = fmaxf(r.y, ay); r.z = fmaxf(r.z, az); r.w = fmaxf(r.w, aw); }
            else        { r.x += ax; r.y += ay; r.z += az; r.w += aw; }
        }
        if (tid == 0) ((float4*)red)[8] = r;
    }
    __syncthreads();
    float4 out = ((float4*)red)[8];
    __syncthreads();
    return out;
}

// ---------------- K0: per-node precompute ----------------
__global__ void prenode_kernel(const float* __restrict__ h,
                               const float* __restrict__ W_in,
                               const float* __restrict__ W_o1) {
    __shared__ float hs[FF];
    int node = blockIdx.x, t = threadIdx.x;
    if (t < FF) hs[t] = h[node * FF + t];
    __syncthreads();
    if (t < KK) {
        float a = 0.f, bv = 0.f;
        #pragma unroll
        for (int f = 0; f < FF; f++) { float hv = hs[f]; a += hv * W_in[f*KK+t]; bv += hv * W_in[(FF+f)*KK+t]; }
        g_A[node*KK+t] = a; g_Bb[node*KK+t] = bv;
    } else if (t >= 64 && t < 128) {
        int c = t - 64;
        float u = 0.f, w = 0.f;
        #pragma unroll
        for (int f = 0; f < FF; f++) { float hv = hs[f]; u += hv * W_o1[f*HH+c]; w += hv * W_o1[(FF+f)*HH+c]; }
        g_U[node*HH+c] = u; g_Wp[node*HH+c] = w;
    }
}

// ================= K1: phases 0-2 per node =================
#define K1_HE    0
#define K1_ATT   16640
#define K1_XDN   17664
#define K1_WIB   18688
#define K1_WON   18752
#define K1_BO2   18816
#define K1_BI    18880
#define K1_MEAN  18944
#define K1_BETA  19008
#define K1_WS    19072
#define K1_BSG   19328
#define K1_XI    19336
#define K1_RED   19340
#define K1_AS    19392
#define K1_WO1K  32448
#define K1_WO2   35648
#define K1_FLOATS 39744
#define K1_BYTES  (K1_FLOATS*4)

__global__ __launch_bounds__(256, 1)
void sake_k1(const float* __restrict__ x,
             const float* __restrict__ means, const float* __restrict__ betas,
             const float* __restrict__ b_in,
             const float* __restrict__ W_o1, const float* __restrict__ b_o1,
             const float* __restrict__ b_o2,
             const float* __restrict__ W_o2,
             const float* __restrict__ Ws,  const float* __restrict__ bs,
             const float* __restrict__ log_gamma) {
    extern __shared__ float sm[];
    const int tid = threadIdx.x;
    const int bid = blockIdx.x, b = bid >> 8, i = bid & 255, nodeI = bid;

    float* he    = sm + K1_HE;
    float* att_s = sm + K1_ATT;
    float* xdn   = sm + K1_XDN;
    float* wib   = sm + K1_WIB;
    float* won   = sm + K1_WON;
    float* bo2_s = sm + K1_BO2;
    float* bi_s  = sm + K1_BI;
    float* mn_s  = sm + K1_MEAN;
    float* bt_s  = sm + K1_BETA;
    float* ws_s  = sm + K1_WS;
    float* bsg   = sm + K1_BSG;
    float* xi_s  = sm + K1_XI;
    float* red   = sm + K1_RED;
    float* As    = sm + K1_AS;
    float* wo1k  = sm + K1_WO1K;
    float* wo2   = sm + K1_WO2;

    if (tid == 0) g_cnt[nodeI] = 0;   // reset tail counter for this launch
    if (tid < FF) {
        wib[tid]   = g_Wp[nodeI*HH+tid] + b_o1[tid];
        won[tid]   = W_o1[178*HH+tid];
        bo2_s[tid] = b_o2[tid];
    }
    if (tid < KK) {
        bi_s[tid] = g_Bb[nodeI*KK+tid] + b_in[tid];
        mn_s[tid] = means[tid];
        bt_s[tid] = betas[tid];
    }
    ws_s[tid] = Ws[tid];
    if (tid < 4) {
        bsg[tid]   = bs[tid];
        bsg[4+tid] = __expf(log_gamma[tid]);
        if (tid < 3) xi_s[tid] = x[nodeI*3+tid];
    }
    for (int idx = tid; idx < NN*KK; idx += 256) {
        int j2 = idx / KK, k = idx - j2*KK;
        As[j2*51+k] = g_A[b*NN*KK + idx];
    }
    for (int idx = tid; idx < NN*HH; idx += 256) {
        int j2 = idx >> 6, f = idx & 63;
        he[j2*65+f] = g_U[b*NN*HH + idx];
    }
    for (int idx = tid; idx < KK*HH; idx += 256) wo1k[idx] = W_o1[128*HH + idx];
    for (int idx = tid; idx < HH*HH; idx += 256) wo2[idx]  = W_o2[idx];
    __syncthreads();

    const int j = tid;
    float xjx = x[(b*NN+j)*3+0], xjy = x[(b*NN+j)*3+1], xjz = x[(b*NN+j)*3+2];
    float dx = xjx - xi_s[0], dy = xjy - xi_s[1], dz = xjz - xi_s[2];
    float d2 = fmaxf(dx*dx + dy*dy + dz*dz, 0.f);
    float normv = sqrtf(d2 + 1e-5f);
    float rinv  = __fdividef(1.f, normv + 1e-5f);
    *(float4*)&xdn[j*4] = make_float4(dx*rinv, dy*rinv, dz*rinv, normv);
    float en = __expf(-normv);

    {
        float accf[64];
        #pragma unroll
        for (int f = 0; f < 64; f++) accf[f] = he[j*65+f] + wib[f] + normv*won[f];
        ull acc2[32];
        #pragma unroll
        for (int f2 = 0; f2 < 32; f2++) acc2[f2] = pack2(accf[2*f2], accf[2*f2+1]);

        #pragma unroll 2
        for (int k = 0; k < KK; k++) {
            float hk = As[j*51+k] + bi_s[k];
            float df = en - mn_s[k];
            float s  = __expf(-bt_s[k]*df*df) * hk;
            ull s2 = bcast2(s);
            const ulonglong2* wr = (const ulonglong2*)&wo1k[k*64];
            #pragma unroll
            for (int f4 = 0; f4 < 16; f4++) {
                ulonglong2 wv = wr[f4];
                fma2(acc2[2*f4],   wv.x, s2);
                fma2(acc2[2*f4+1], wv.y, s2);
            }
        }
        #pragma unroll
        for (int f2 = 0; f2 < 32; f2++) {
            float a0, a1; unpack2(acc2[f2], a0, a1);
            accf[2*f2] = siluf(a0); accf[2*f2+1] = siluf(a1);
        }

        #pragma unroll
        for (int g = 0; g < 4; g++) {
            ull o2[8];
            const ulonglong2* bo = (const ulonglong2*)&bo2_s[g*16];
            #pragma unroll
            for (int q = 0; q < 4; q++) { ulonglong2 bv = bo[q]; o2[2*q] = bv.x; o2[2*q+1] = bv.y; }
            #pragma unroll 8
            for (int f = 0; f < 64; f++) {
                ull ab = bcast2(accf[f]);
                const ulonglong2* wr = (const ulonglong2*)&wo2[f*64 + g*16];
                #pragma unroll
                for (int q = 0; q < 4; q++) {
                    ulonglong2 wv = wr[q];
                    fma2(o2[2*q],   wv.x, ab);
                    fma2(o2[2*q+1], wv.y, ab);
                }
            }
            #pragma unroll
            for (int q = 0; q < 8; q++) {
                float r0, r1; unpack2(o2[q], r0, r1);
                he[j*65 + g*16 + 2*q]     = r0;
                he[j*65 + g*16 + 2*q + 1] = r1;
            }
        }
    }

    float z0, z1, z2, z3;
    {
        ull z01 = pack2(bsg[0], bsg[1]);
        ull z23 = pack2(bsg[2], bsg[3]);
        #pragma unroll 8
        for (int f = 0; f < 64; f++) {
            ull ab = bcast2(he[j*65+f]);
            ulonglong2 wv = *(const ulonglong2*)&ws_s[f*4];
            fma2(z01, wv.x, ab);
            fma2(z23, wv.y, ab);
        }
        unpack2(z01, z0, z1);
        unpack2(z23, z2, z3);
    }
    z0 = (z0 > 0.f) ? z0 : 2.f*(__expf(0.5f*z0) - 1.f);
    z1 = (z1 > 0.f) ? z1 : 2.f*(__expf(0.5f*z1) - 1.f);
    z2 = (z2 > 0.f) ? z2 : 2.f*(__expf(0.5f*z2) - 1.f);
    z3 = (z3 > 0.f) ? z3 : 2.f*(__expf(0.5f*z3) - 1.f);
    float diag = (j == i) ? 1e5f : 0.f;
    float4 el = make_float4(-(normv+diag)*bsg[4], -(normv+diag)*bsg[5],
                            -(normv+diag)*bsg[6], -(normv+diag)*bsg[7]);
    float4 sl = make_float4(z0-diag, z1-diag, z2-diag, z3-diag);

    float4 m  = block_red4<1>(el, tid, red);
    float4 ee = make_float4(__expf(el.x-m.x), __expf(el.y-m.y), __expf(el.z-m.z), __expf(el.w-m.w));
    float4 s  = block_red4<0>(ee, tid, red);
    float4 eucl = make_float4(__fdividef(ee.x,s.x), __fdividef(ee.y,s.y),
                              __fdividef(ee.z,s.z), __fdividef(ee.w,s.w));
    m  = block_red4<1>(sl, tid, red);
    ee = make_float4(__expf(sl.x-m.x), __expf(sl.y-m.y), __expf(sl.z-m.z), __expf(sl.w-m.w));
    s  = block_red4<0>(ee, tid, red);
    float4 sem = make_float4(__fdividef(ee.x,s.x), __fdividef(ee.y,s.y),
                             __fdividef(ee.z,s.z), __fdividef(ee.w,s.w));
    float4 q4 = make_float4(eucl.x*sem.x, eucl.y*sem.y, eucl.z*sem.z, eucl.w*sem.w);
    m  = block_red4<1>(q4, tid, red);
    ee = make_float4(__expf(q4.x-m.x), __expf(q4.y-m.y), __expf(q4.z-m.z), __expf(q4.w-m.w));
    s  = block_red4<0>(ee, tid, red);
    att_s[j*4+0] = __fdividef(ee.x, s.x);
    att_s[j*4+1] = __fdividef(ee.y, s.y);
    att_s[j*4+2] = __fdividef(ee.z, s.z);
    att_s[j*4+3] = __fdividef(ee.w, s.w);
    __syncthreads();

    for (int idx = tid; idx < NN*FF; idx += 256)
        g_he[nodeI*(NN*FF) + idx] = he[(idx >> 6)*65 + (idx & 63)];
    for (int idx = tid; idx < NN*4; idx += 256) {
        g_attG[nodeI*(NN*4) + idx] = att_s[idx];
        g_xdnG[nodeI*(NN*4) + idx] = xdn[idx];
    }
}

// ================= K2: phase 4 + fused tail (last block per node) =================
#define K2_HEH   0
#define K2_ATT   8320
#define K2_XDN   8832
#define K2_HET   9344
#define K2_WCH   28800
#define K2_FLOATS 45184
#define K2_BYTES  (K2_FLOATS*4)
// tail view (aliases heH region, dead after main loop):
#define T_CN    0      // 256
#define T_PART  256    // 256
#define T_CAT   512    // 384
#define T_P1    896    // 64
#define T_N1    960    // 64
#define T_HN    1024   // 64
#define T_HI    1088   // 64
#define T_RED   1152   // 40 (byte 4608, 16B aligned)

__global__ __launch_bounds__(256, 1)
void sake_k2(const float* __restrict__ Wx,
             const float* __restrict__ h, const float* __restrict__ x,
             const float* __restrict__ v,
             const float* __restrict__ Wv_mix,
             const float* __restrict__ Wp1, const float* __restrict__ bp1,
             const float* __restrict__ Wp2, const float* __restrict__ bp2,
             const float* __restrict__ Wn1, const float* __restrict__ bn1,
             const float* __restrict__ Wn2, const float* __restrict__ bn2,
             const float* __restrict__ Wvel1, const float* __restrict__ bvel1,
             const float* __restrict__ Wvel2,
             float* __restrict__ outH, float* __restrict__ outX,
             float* __restrict__ outV) {
    extern __shared__ float sm[];
    const int tid = threadIdx.x, wid = tid >> 5, lane = tid & 31;
    const int bid = blockIdx.x;
    const int node = bid >> 1, jh = bid & 1;

    float* heH  = sm + K2_HEH;
    float* attH = sm + K2_ATT;
    float* xdnH = sm + K2_XDN;
    float* heT  = sm + K2_HET;
    const uint32_t smb = smem_u32(sm);

    for (int idx = tid; idx < 128*FF; idx += 256)
        heH[(idx >> 6)*65 + (idx & 63)] = g_he[node*(NN*FF) + jh*(128*FF) + idx];
    for (int idx = tid; idx < 512; idx += 256) {
        attH[idx] = g_attG[node*(NN*4) + jh*512 + idx];
        xdnH[idx] = g_xdnG[node*(NN*4) + jh*512 + idx];
    }
    __syncthreads();

    const int jp = lane >> 3, nq = lane & 7;
    const int nb = wid*32 + nq*4;
    const int fme = tid >> 2, hme = tid & 3;
    float cmx[4] = {0,0,0,0}, cmy[4] = {0,0,0,0}, cmz[4] = {0,0,0,0};
    float heE = 0.f;

    #define STAGE(chunk, buf) do { \
        uint32_t _dst = smb + (uint32_t)(K2_WCH + (buf)*8192)*4u + (uint32_t)tid*16u; \
        const float* _src = Wx + (chunk)*8192 + tid*4; \
        _Pragma("unroll") \
        for (int _r = 0; _r < 8; _r++) cp16(_dst + _r*4096u, _src + _r*1024); \
        CP_COMMIT(); \
    } while(0)

    for (int pass = 0; pass < 2; pass++) {
        const int j0 = pass*64;
        const int sgn = (8 - 2*pass) & 7;
        __syncthreads();
        if (pass == 0) STAGE(0, 0);
        #pragma unroll 8
        for (int jj = 0; jj < 64; jj += 2) {
            int jn = j0 + jj;
            float v0 = heH[jn*65 + fme]     * attH[jn*4 + hme];
            float v1 = heH[(jn+1)*65 + fme] * attH[(jn+1)*4 + hme];
            heE += v0 + v1;
            int off = ((jj >> 4)*20) + (jj & 15);
            *(ull*)&heT[tid*76 + off] = pack2(v0, v1);
        }

        ull acc[4][8];
        #pragma unroll
        for (int n = 0; n < 4; n++)
            #pragma unroll
            for (int p = 0; p < 8; p++) acc[n][p] = 0ull;

        for (int t = 0; t < 8; t++) {
            const int ck = (sgn + t) & 7;
            if (pass == 0 || t >= 2) CP_WAIT0();
            __syncthreads();
            if (t < 7 && (pass == 0 || t >= 1)) STAGE((sgn + t + 1) & 7, (t+1)&1);

            const float* ar = heT + (ck*32)*76 + jp*20;
            const float* wr = sm + K2_WCH + (t&1)*8192 + nb;
            #pragma unroll 8
            for (int cc = 0; cc < 32; cc++) {
                ulonglong2 a0 = *(const ulonglong2*)(ar);
                ulonglong2 a1 = *(const ulonglong2*)(ar + 4);
                ulonglong2 a2 = *(const ulonglong2*)(ar + 8);
                ulonglong2 a3 = *(const ulonglong2*)(ar + 12);
                float4 w4 = *(const float4*)(wr);
                ull bb0 = bcast2(w4.x), bb1 = bcast2(w4.y);
                ull bb2 = bcast2(w4.z), bb3 = bcast2(w4.w);
                fma2(acc[0][0], a0.x, bb0); fma2(acc[0][1], a0.y, bb0);
                fma2(acc[0][2], a1.x, bb0); fma2(acc[0][3], a1.y, bb0);
                fma2(acc[0][4], a2.x, bb0); fma2(acc[0][5], a2.y, bb0);
                fma2(acc[0][6], a3.x, bb0); fma2(acc[0][7], a3.y, bb0);
                fma2(acc[1][0], a0.x, bb1); fma2(acc[1][1], a0.y, bb1);
                fma2(acc[1][2], a1.x, bb1); fma2(acc[1][3], a1.y, bb1);
                fma2(acc[1][4], a2.x, bb1); fma2(acc[1][5], a2.y, bb1);
                fma2(acc[1][6], a3.x, bb1); fma2(acc[1][7], a3.y, bb1);
                fma2(acc[2][0], a0.x, bb2); fma2(acc[2][1], a0.y, bb2);
                fma2(acc[2][2], a1.x, bb2); fma2(acc[2][3], a1.y, bb2);
                fma2(acc[2][4], a2.x, bb2); fma2(acc[2][5], a2.y, bb2);
                fma2(acc[2][6], a3.x, bb2); fma2(acc[2][7], a3.y, bb2);
                fma2(acc[3][0], a0.x, bb3); fma2(acc[3][1], a0.y, bb3);
                fma2(acc[3][2], a1.x, bb3); fma2(acc[3][3], a1.y, bb3);
                fma2(acc[3][4], a2.x, bb3); fma2(acc[3][5], a2.y, bb3);
                fma2(acc[3][6], a3.x, bb3); fma2(acc[3][7], a3.y, bb3);
                ar += 76; wr += 256;
            }
        }

        #pragma unroll
        for (int p = 0; p < 8; p++) {
            float4 x0 = *(const float4*)&xdnH[(j0 + jp*16 + 2*p)*4];
            float4 x1 = *(const float4*)&xdnH[(j0 + jp*16 + 2*p + 1)*4];
            #pragma unroll
            for (int n = 0; n < 4; n++) {
                float c0, c1; unpack2(acc[n][p], c0, c1);
                float t0 = ftanh(c0), t1 = ftanh(c1);
                cmx[n] += x0.x*t0 + x1.x*t1;
                cmy[n] += x0.y*t0 + x1.y*t1;
                cmz[n] += x0.z*t0 + x1.z*t1;
            }
        }
    }
    g_heE[node*512 + jh*256 + tid] = heE;

    #pragma unroll
    for (int n = 0; n < 4; n++) {
        #pragma unroll
        for (int o = 8; o <= 16; o <<= 1) {
            cmx[n] += __shfl_xor_sync(~0u, cmx[n], o);
            cmy[n] += __shfl_xor_sync(~0u, cmy[n], o);
            cmz[n] += __shfl_xor_sync(~0u, cmz[n], o);
        }
    }
    if (jp == 0) {
        const int base = node*1536 + jh*768;
        #pragma unroll
        for (int n = 0; n < 4; n++) {
            g_cmp[base +       nb + n] = cmx[n];
            g_cmp[base + 256 + nb + n] = cmy[n];
            g_cmp[base + 512 + nb + n] = cmz[n];
        }
    }

    // ---- tail gating: last block of this node runs phases 5-6 ----
    __threadfence();
    __syncthreads();
    __shared__ int isLast;
    if (tid == 0) isLast = (atomicAdd(&g_cnt[node], 1) == 1) ? 1 : 0;
    __syncthreads();
    if (!isLast) return;
    __threadfence();

    float* cn    = sm + T_CN;
    float* part  = sm + T_PART;
    float* cat   = sm + T_CAT;
    float* p1_s  = sm + T_P1;
    float* n1_s  = sm + T_N1;
    float* hn_s  = sm + T_HN;
    float* hi_s  = sm + T_HI;
    float* redt  = sm + T_RED;
    __syncthreads();   // heH region reads done (main loop long past); safe to overwrite

    const float invN = 1.f/256.f;
    const int base = node*1536;
    float csx = (g_cmp[base + tid]       + g_cmp[base + 768 + tid])  * invN;
    float csy = (g_cmp[base + 256 + tid] + g_cmp[base + 1024 + tid]) * invN;
    float csz = (g_cmp[base + 512 + tid] + g_cmp[base + 1280 + tid]) * invN;
    cn[tid] = csx*csx + csy*csy + csz*csz;
    float wv = Wv_mix[tid];
    cat[64 + tid] = g_heE[node*512 + tid] + g_heE[node*512 + 256 + tid];
    if (tid < 64) { float hv = h[node*64 + tid]; cat[tid] = hv; hi_s[tid] = hv; }
    float4 dv4 = block_red4<0>(make_float4(wv*csx, wv*csy, wv*csz, 0.f), tid, redt);

    const int g6 = tid >> 6, o6 = tid & 63;
    {   // p1: 256 -> 64
        float a = 0.f;
        const float* wp = Wp1 + g6*64*64 + o6;
        const float* cnp = cn + g6*64;
        #pragma unroll 4
        for (int c = 0; c < 64; c++) a += cnp[c] * wp[c*64];
        part[tid] = a;
    }
    __syncthreads();
    if (tid < 64) {
        float a = bp1[tid] + part[tid] + part[64+tid] + part[128+tid] + part[192+tid];
        p1_s[tid] = siluf(a);
    }
    __syncthreads();
    {   // p2: 64 -> 64
        float a = 0.f;
        const float* wp = Wp2 + g6*16*64 + o6;
        #pragma unroll
        for (int f = 0; f < 16; f++) a += p1_s[g6*16+f] * wp[f*64];
        part[tid] = a;
    }
    __syncthreads();
    if (tid < 64) {
        float a = bp2[tid] + part[tid] + part[64+tid] + part[128+tid] + part[192+tid];
        float hc = siluf(a);
        cat[320 + tid] = hc;
    }
    __syncthreads();
    {   // n1: 384 -> 64
        float a = 0.f;
        const float* wp = Wn1 + g6*96*64 + o6;
        const float* cp = cat + g6*96;
        #pragma unroll 4
        for (int r = 0; r < 96; r++) a += cp[r] * wp[r*64];
        part[tid] = a;
    }
    __syncthreads();
    if (tid < 64) {
        float a = bn1[tid] + part[tid] + part[64+tid] + part[128+tid] + part[192+tid];
        n1_s[tid] = siluf(a);
    }
    __syncthreads();
    {   // n2: 64 -> 64
        float a = 0.f;
        const float* wp = Wn2 + g6*16*64 + o6;
        #pragma unroll
        for (int f = 0; f < 16; f++) a += n1_s[g6*16+f] * wp[f*64];
        part[tid] = a;
    }
    __syncthreads();
    if (tid < 64) {
        float a = bn2[tid] + part[tid] + part[64+tid] + part[128+tid] + part[192+tid];
        float hv = hi_s[tid] + siluf(a);
        hn_s[tid] = hv;
        outH[node*64+tid] = hv;
    }
    __syncthreads();
    {   // vel1: 64 -> 64
        float a = 0.f;
        const float* wp = Wvel1 + g6*16*64 + o6;
        #pragma unroll
        for (int f = 0; f < 16; f++) a += hn_s[g6*16+f] * wp[f*64];
        part[tid] = a;
    }
    __syncthreads();
    float vl = 0.f;
    if (tid < 64) {
        float a = bvel1[tid] + part[tid] + part[64+tid] + part[128+tid] + part[192+tid];
        vl = siluf(a) * Wvel2[tid];
    }
    float4 vs = block_red4<0>(make_float4(vl, 0.f, 0.f, 0.f), tid, redt);
    if (tid == 0) {
        float scale = 2.f * sigm(vs.x);
        float dvv[3] = {dv4.x, dv4.y, dv4.z};
        #pragma unroll
        for (int t = 0; t < 3; t++) {
            float vn = dvv[t] + scale * v[node*3+t];
            outV[node*3+t] = vn;
            outX[node*3+t] = x[node*3+t] + vn;
        }
    }
}

// ---------------- launch ----------------
extern "C" void kernel_launch(void* const* d_in, const int* in_sizes, int n_in,
                              void* d_out, int out_size) {
    const float* h      = (const float*)d_in[0];
    const float* x      = (const float*)d_in[1];
    const float* v      = (const float*)d_in[2];
    const float* means  = (const float*)d_in[3];
    const float* betas  = (const float*)d_in[4];
    const float* W_in   = (const float*)d_in[5];
    const float* b_in   = (const float*)d_in[6];
    const float* W_o1   = (const float*)d_in[7];
    const float* b_o1   = (const float*)d_in[8];
    const float* W_o2   = (const float*)d_in[9];
    const float* b_o2   = (const float*)d_in[10];
    const float* Ws     = (const float*)d_in[11];
    const float* bs     = (const float*)d_in[12];
    const float* lgam   = (const float*)d_in[13];
    const float* Wx     = (const float*)d_in[14];
    const float* Wp1    = (const float*)d_in[15];
    const float* bp1    = (const float*)d_in[16];
    const float* Wp2    = (const float*)d_in[17];
    const float* bp2    = (const float*)d_in[18];
    const float* Wn1    = (const float*)d_in[19];
    const float* bn1    = (const float*)d_in[20];
    const float* Wn2    = (const float*)d_in[21];
    const float* bn2    = (const float*)d_in[22];
    const float* Wv_mix = (const float*)d_in[23];
    const float* Wvel1  = (const float*)d_in[24];
    const float* bvel1  = (const float*)d_in[25];
    const float* Wvel2  = (const float*)d_in[26];

    float* out  = (float*)d_out;
    float* outH = out;
    float* outX = out + BB*NN*FF;
    float* outV = outX + BB*NN*3;

    cudaFuncSetAttribute(sake_k1, cudaFuncAttributeMaxDynamicSharedMemorySize, K1_BYTES);
    cudaFuncSetAttribute(sake_k2, cudaFuncAttributeMaxDynamicSharedMemorySize, K2_BYTES);

    prenode_kernel<<<BB*NN, 128>>>(h, W_in, W_o1);
    sake_k1<<<BB*NN, 256, K1_BYTES>>>(x, means, betas, b_in, W_o1, b_o1, b_o2, W_o2,
                                      Ws, bs, lgam);
    sake_k2<<<BB*NN*2, 256, K2_BYTES>>>(Wx, h, x, v, Wv_mix, Wp1, bp1, Wp2, bp2,
                                        Wn1, bn1, Wn2, bn2, Wvel1, bvel1, Wvel2,
                                        outH, outX, outV);
}

// round 17
// speedup vs baseline: 1.1539x; 1.1539x over previous
#include <cuda_runtime.h>
#include <cstdint>

#define BB 2
#define NN 256
#define FF 64
#define HH 64
#define KK 50
#define CC 256

// ---------------- device scratch ----------------
__device__ float g_A [BB*NN*KK];
__device__ float g_Bb[BB*NN*KK];
__device__ float g_U [BB*NN*HH];
__device__ float g_Wp[BB*NN*HH];
__device__ float g_he  [BB*NN*NN*FF];
__device__ float g_attG[BB*NN*NN*4];
__device__ float g_xdnG[BB*NN*NN*4];
__device__ float g_cmp [BB*NN*2*3*CC];
__device__ float g_heE [BB*NN*2*CC];

typedef unsigned long long ull;

// ---------------- helpers ----------------
__device__ __forceinline__ uint32_t smem_u32(const void* p) {
    uint32_t a;
    asm("{ .reg .u64 t; cvta.to.shared.u64 t, %1; cvt.u32.u64 %0, t; }" : "=r"(a) : "l"(p));
    return a;
}
__device__ __forceinline__ float siluf(float a) { return a * __fdividef(1.f, 1.f + __expf(-a)); }
__device__ __forceinline__ float sigm(float a)  { return __fdividef(1.f, 1.f + __expf(-a)); }
__device__ __forceinline__ float ftanh(float x) {
    float e = __expf(-2.f * fabsf(x));
    return copysignf(__fdividef(1.f - e, 1.f + e), x);
}
__device__ __forceinline__ void fma2(ull& acc, ull a, ull b) {
    asm("fma.rn.f32x2 %0, %1, %2, %0;" : "+l"(acc) : "l"(a), "l"(b));
}
__device__ __forceinline__ ull bcast2(float w) {
    ull r; asm("mov.b64 %0, {%1, %1};" : "=l"(r) : "f"(w)); return r;
}
__device__ __forceinline__ ull pack2(float a, float b) {
    ull r; asm("mov.b64 %0, {%1, %2};" : "=l"(r) : "f"(a), "f"(b)); return r;
}
__device__ __forceinline__ void unpack2(ull v, float& x, float& y) {
    asm("mov.b64 {%0, %1}, %2;" : "=f"(x), "=f"(y) : "l"(v));
}
__device__ __forceinline__ void cp16(uint32_t dst, const void* src) {
    asm volatile("cp.async.cg.shared.global [%0], [%1], 16;" :: "r"(dst), "l"(src) : "memory");
}
#define CP_COMMIT() asm volatile("cp.async.commit_group;" ::: "memory")
#define CP_WAIT0()  asm volatile("cp.async.wait_group 0;" ::: "memory")

// block reduce of 4 floats (8 warps / 256 threads). red >= 36 floats, 16B aligned.
template<int DO_MAX>
__device__ __forceinline__ float4 block_red4(float4 v, int tid, float* red) {
    #pragma unroll
    for (int o = 16; o > 0; o >>= 1) {
        float ax = __shfl_xor_sync(~0u, v.x, o), ay = __shfl_xor_sync(~0u, v.y, o);
        float az = __shfl_xor_sync(~0u, v.z, o), aw = __shfl_xor_sync(~0u, v.w, o);
        if (DO_MAX) { v.x = fmaxf(v.x, ax); v.y = fmaxf(v.y, ay); v.z = fmaxf(v.z, az); v.w = fmaxf(v.w, aw); }
        else        { v.x += ax; v.y += ay; v.z += az; v.w += aw; }
    }
    if ((tid & 31) == 0) ((float4*)red)[tid >> 5] = v;
    __syncthreads();
    if (tid < 32) {
        float4 r;
        if (tid < 8) r = ((float4*)red)[tid];
        else { float id = DO_MAX ? __int_as_float(0xff800000) : 0.f; r = make_float4(id, id, id, id); }
        #pragma unroll
        for (int o = 4; o > 0; o >>= 1) {
            float ax = __shfl_xor_sync(~0u, r.x, o), ay = __shfl_xor_sync(~0u, r.y, o);
            float az = __shfl_xor_sync(~0u, r.z, o), aw = __shfl_xor_sync(~0u, r.w, o);
            if (DO_MAX) { r.x = fmaxf(r.x, ax); r.y = fmaxf(r.y, ay); r.z = fmaxf(r.z, az); r.w = fmaxf(r.w, aw); }
            else        { r.x += ax; r.y += ay; r.z += az; r.w += aw; }
        }
        if (tid == 0) ((float4*)red)[8] = r;
    }
    __syncthreads();
    float4 out = ((float4*)red)[8];
    __syncthreads();
    return out;
}

// ---------------- K0: per-node precompute ----------------
__global__ void prenode_kernel(const float* __restrict__ h,
                               const float* __restrict__ W_in,
                               const float* __restrict__ W_o1) {
    __shared__ float hs[FF];
    int node = blockIdx.x, t = threadIdx.x;
    if (t < FF) hs[t] = h[node * FF + t];
    __syncthreads();
    if (t < KK) {
        float a = 0.f, bv = 0.f;
        #pragma unroll
        for (int f = 0; f < FF; f++) { float hv = hs[f]; a += hv * W_in[f*KK+t]; bv += hv * W_in[(FF+f)*KK+t]; }
        g_A[node*KK+t] = a; g_Bb[node*KK+t] = bv;
    } else if (t >= 64 && t < 128) {
        int c = t - 64;
        float u = 0.f, w = 0.f;
        #pragma unroll
        for (int f = 0; f < FF; f++) { float hv = hs[f]; u += hv * W_o1[f*HH+c]; w += hv * W_o1[(FF+f)*HH+c]; }
        g_U[node*HH+c] = u; g_Wp[node*HH+c] = w;
    }
}

// ================= K1: phases 0-2 per node =================
#define K1_HE    0
#define K1_ATT   16640
#define K1_XDN   17664
#define K1_WIB   18688
#define K1_WON   18752
#define K1_BO2   18816
#define K1_BI    18880
#define K1_MEAN  18944
#define K1_BETA  19008
#define K1_WS    19072
#define K1_BSG   19328
#define K1_XI    19336
#define K1_RED   19340
#define K1_AS    19392
#define K1_WO1K  32448
#define K1_WO2   35648
#define K1_FLOATS 39744
#define K1_BYTES  (K1_FLOATS*4)

__global__ __launch_bounds__(256, 1)
void sake_k1(const float* __restrict__ x,
             const float* __restrict__ means, const float* __restrict__ betas,
             const float* __restrict__ b_in,
             const float* __restrict__ W_o1, const float* __restrict__ b_o1,
             const float* __restrict__ b_o2,
             const float* __restrict__ W_o2,
             const float* __restrict__ Ws,  const float* __restrict__ bs,
             const float* __restrict__ log_gamma) {
    extern __shared__ float sm[];
    const int tid = threadIdx.x;
    const int bid = blockIdx.x, b = bid >> 8, i = bid & 255, nodeI = bid;

    float* he    = sm + K1_HE;
    float* att_s = sm + K1_ATT;
    float* xdn   = sm + K1_XDN;
    float* wib   = sm + K1_WIB;
    float* won   = sm + K1_WON;
    float* bo2_s = sm + K1_BO2;
    float* bi_s  = sm + K1_BI;
    float* mn_s  = sm + K1_MEAN;
    float* bt_s  = sm + K1_BETA;
    float* ws_s  = sm + K1_WS;
    float* bsg   = sm + K1_BSG;
    float* xi_s  = sm + K1_XI;
    float* red   = sm + K1_RED;
    float* As    = sm + K1_AS;
    float* wo1k  = sm + K1_WO1K;
    float* wo2   = sm + K1_WO2;

    if (tid < FF) {
        wib[tid]   = g_Wp[nodeI*HH+tid] + b_o1[tid];
        won[tid]   = W_o1[178*HH+tid];
        bo2_s[tid] = b_o2[tid];
    }
    if (tid < KK) {
        bi_s[tid] = g_Bb[nodeI*KK+tid] + b_in[tid];
        mn_s[tid] = means[tid];
        bt_s[tid] = betas[tid];
    }
    ws_s[tid] = Ws[tid];
    if (tid < 4) {
        bsg[tid]   = bs[tid];
        bsg[4+tid] = __expf(log_gamma[tid]);
        if (tid < 3) xi_s[tid] = x[nodeI*3+tid];
    }
    for (int idx = tid; idx < NN*KK; idx += 256) {
        int j2 = idx / KK, k = idx - j2*KK;
        As[j2*51+k] = g_A[b*NN*KK + idx];
    }
    for (int idx = tid; idx < NN*HH; idx += 256) {
        int j2 = idx >> 6, f = idx & 63;
        he[j2*65+f] = g_U[b*NN*HH + idx];
    }
    for (int idx = tid; idx < KK*HH; idx += 256) wo1k[idx] = W_o1[128*HH + idx];
    for (int idx = tid; idx < HH*HH; idx += 256) wo2[idx]  = W_o2[idx];
    __syncthreads();

    const int j = tid;
    float xjx = x[(b*NN+j)*3+0], xjy = x[(b*NN+j)*3+1], xjz = x[(b*NN+j)*3+2];
    float dx = xjx - xi_s[0], dy = xjy - xi_s[1], dz = xjz - xi_s[2];
    float d2 = fmaxf(dx*dx + dy*dy + dz*dz, 0.f);
    float normv = sqrtf(d2 + 1e-5f);
    float rinv  = __fdividef(1.f, normv + 1e-5f);
    *(float4*)&xdn[j*4] = make_float4(dx*rinv, dy*rinv, dz*rinv, normv);
    float en = __expf(-normv);

    {
        float accf[64];
        #pragma unroll
        for (int f = 0; f < 64; f++) accf[f] = he[j*65+f] + wib[f] + normv*won[f];
        ull acc2[32];
        #pragma unroll
        for (int f2 = 0; f2 < 32; f2++) acc2[f2] = pack2(accf[2*f2], accf[2*f2+1]);

        #pragma unroll 2
        for (int k = 0; k < KK; k++) {
            float hk = As[j*51+k] + bi_s[k];
            float df = en - mn_s[k];
            float s  = __expf(-bt_s[k]*df*df) * hk;
            ull s2 = bcast2(s);
            const ulonglong2* wr = (const ulonglong2*)&wo1k[k*64];
            #pragma unroll
            for (int f4 = 0; f4 < 16; f4++) {
                ulonglong2 wv = wr[f4];
                fma2(acc2[2*f4],   wv.x, s2);
                fma2(acc2[2*f4+1], wv.y, s2);
            }
        }
        #pragma unroll
        for (int f2 = 0; f2 < 32; f2++) {
            float a0, a1; unpack2(acc2[f2], a0, a1);
            accf[2*f2] = siluf(a0); accf[2*f2+1] = siluf(a1);
        }

        #pragma unroll
        for (int g = 0; g < 4; g++) {
            ull o2[8];
            const ulonglong2* bo = (const ulonglong2*)&bo2_s[g*16];
            #pragma unroll
            for (int q = 0; q < 4; q++) { ulonglong2 bv = bo[q]; o2[2*q] = bv.x; o2[2*q+1] = bv.y; }
            #pragma unroll 8
            for (int f = 0; f < 64; f++) {
                ull ab = bcast2(accf[f]);
                const ulonglong2* wr = (const ulonglong2*)&wo2[f*64 + g*16];
                #pragma unroll
                for (int q = 0; q < 4; q++) {
                    ulonglong2 wv = wr[q];
                    fma2(o2[2*q],   wv.x, ab);
                    fma2(o2[2*q+1], wv.y, ab);
                }
            }
            #pragma unroll
            for (int q = 0; q < 8; q++) {
                float r0, r1; unpack2(o2[q], r0, r1);
                he[j*65 + g*16 + 2*q]     = r0;
                he[j*65 + g*16 + 2*q + 1] = r1;
            }
        }
    }

    float z0, z1, z2, z3;
    {
        ull z01 = pack2(bsg[0], bsg[1]);
        ull z23 = pack2(bsg[2], bsg[3]);
        #pragma unroll 8
        for (int f = 0; f < 64; f++) {
            ull ab = bcast2(he[j*65+f]);
            ulonglong2 wv = *(const ulonglong2*)&ws_s[f*4];
            fma2(z01, wv.x, ab);
            fma2(z23, wv.y, ab);
        }
        unpack2(z01, z0, z1);
        unpack2(z23, z2, z3);
    }
    z0 = (z0 > 0.f) ? z0 : 2.f*(__expf(0.5f*z0) - 1.f);
    z1 = (z1 > 0.f) ? z1 : 2.f*(__expf(0.5f*z1) - 1.f);
    z2 = (z2 > 0.f) ? z2 : 2.f*(__expf(0.5f*z2) - 1.f);
    z3 = (z3 > 0.f) ? z3 : 2.f*(__expf(0.5f*z3) - 1.f);
    float diag = (j == i) ? 1e5f : 0.f;
    float4 el = make_float4(-(normv+diag)*bsg[4], -(normv+diag)*bsg[5],
                            -(normv+diag)*bsg[6], -(normv+diag)*bsg[7]);
    float4 sl = make_float4(z0-diag, z1-diag, z2-diag, z3-diag);

    float4 m  = block_red4<1>(el, tid, red);
    float4 ee = make_float4(__expf(el.x-m.x), __expf(el.y-m.y), __expf(el.z-m.z), __expf(el.w-m.w));
    float4 s  = block_red4<0>(ee, tid, red);
    float4 eucl = make_float4(__fdividef(ee.x,s.x), __fdividef(ee.y,s.y),
                              __fdividef(ee.z,s.z), __fdividef(ee.w,s.w));
    m  = block_red4<1>(sl, tid, red);
    ee = make_float4(__expf(sl.x-m.x), __expf(sl.y-m.y), __expf(sl.z-m.z), __expf(sl.w-m.w));
    s  = block_red4<0>(ee, tid, red);
    float4 sem = make_float4(__fdividef(ee.x,s.x), __fdividef(ee.y,s.y),
                             __fdividef(ee.z,s.z), __fdividef(ee.w,s.w));
    float4 q4 = make_float4(eucl.x*sem.x, eucl.y*sem.y, eucl.z*sem.z, eucl.w*sem.w);
    m  = block_red4<1>(q4, tid, red);
    ee = make_float4(__expf(q4.x-m.x), __expf(q4.y-m.y), __expf(q4.z-m.z), __expf(q4.w-m.w));
    s  = block_red4<0>(ee, tid, red);
    att_s[j*4+0] = __fdividef(ee.x, s.x);
    att_s[j*4+1] = __fdividef(ee.y, s.y);
    att_s[j*4+2] = __fdividef(ee.z, s.z);
    att_s[j*4+3] = __fdividef(ee.w, s.w);
    __syncthreads();

    for (int idx = tid; idx < NN*FF; idx += 256)
        g_he[nodeI*(NN*FF) + idx] = he[(idx >> 6)*65 + (idx & 63)];
    for (int idx = tid; idx < NN*4; idx += 256) {
        g_attG[nodeI*(NN*4) + idx] = att_s[idx];
        g_xdnG[nodeI*(NN*4) + idx] = xdn[idx];
    }
}

// ================= K2: phase 4, (node, j-half) blocks =================
#define K2_HEH   0        // [128 j][64] = 8192 (stride 64, cp.async-friendly)
#define K2_ATT   8192     // 512
#define K2_XDN   8704     // 512
#define K2_HET   9216     // heT[256 c][76] = 19456 -> 28672 (byte 36864, 16B ok)
#define K2_WCH   28672    // 2*8192 = 16384 -> 45056 (byte 114688, 16B ok)
#define K2_FLOATS 45056
#define K2_BYTES  (K2_FLOATS*4)   // 180224

__global__ __launch_bounds__(256, 1)
void sake_k2(const float* __restrict__ Wx) {
    extern __shared__ float sm[];
    const int tid = threadIdx.x, wid = tid >> 5, lane = tid & 31;
    const int bid = blockIdx.x;
    const int node = bid >> 1, jh = bid & 1;

    float* heH  = sm + K2_HEH;   // [128 j][64]
    float* attH = sm + K2_ATT;
    float* xdnH = sm + K2_XDN;
    float* heT  = sm + K2_HET;
    const uint32_t smb = smem_u32(sm);

    #define STAGE(chunk, buf) do { \
        uint32_t _dst = smb + (uint32_t)(K2_WCH + (buf)*8192)*4u + (uint32_t)tid*16u; \
        const float* _src = Wx + (chunk)*8192 + tid*4; \
        _Pragma("unroll") \
        for (int _r = 0; _r < 8; _r++) cp16(_dst + _r*4096u, _src + _r*1024); \
        CP_COMMIT(); \
    } while(0)

    // async front-load: heH + att/xdn via cp.async, overlapped with Wx chunk-0 staging
    {
        const float* src = g_he + node*(NN*FF) + jh*(128*FF);
        uint32_t dst = smb + (uint32_t)tid*16u;
        #pragma unroll
        for (int r = 0; r < 8; r++)
            cp16(dst + r*4096u, src + tid*4 + r*1024);
        if (tid < 128) {
            cp16(smb + (uint32_t)K2_ATT*4u + tid*16u, g_attG + node*(NN*4) + jh*512 + tid*4);
            cp16(smb + (uint32_t)K2_XDN*4u + tid*16u, g_xdnG + node*(NN*4) + jh*512 + tid*4);
        }
        CP_COMMIT();
        STAGE(0, 0);
        CP_WAIT0();
        __syncthreads();   // inputs + chunk 0 ready
    }

    const int jp = lane >> 3, nq = lane & 7;
    const int nb = wid*32 + nq*4;
    const int fme = tid >> 2, hme = tid & 3;
    float cmx[4] = {0,0,0,0}, cmy[4] = {0,0,0,0}, cmz[4] = {0,0,0,0};
    float heE = 0.f;

    for (int pass = 0; pass < 2; pass++) {
        const int j0 = pass*64;
        const int sgn = (8 - 2*pass) & 7;
        if (pass) __syncthreads();
        #pragma unroll 8
        for (int jj = 0; jj < 64; jj += 2) {
            int jn = j0 + jj;
            float v0 = heH[jn*64 + fme]     * attH[jn*4 + hme];
            float v1 = heH[(jn+1)*64 + fme] * attH[(jn+1)*4 + hme];
            heE += v0 + v1;
            int off = ((jj >> 4)*20) + (jj & 15);
            *(ull*)&heT[tid*76 + off] = pack2(v0, v1);
        }

        ull acc[4][8];
        #pragma unroll
        for (int n = 0; n < 4; n++)
            #pragma unroll
            for (int p = 0; p < 8; p++) acc[n][p] = 0ull;

        for (int t = 0; t < 8; t++) {
            const int ck = (sgn + t) & 7;
            if (pass == 0 || t >= 2) CP_WAIT0();
            __syncthreads();
            if (t < 7 && (pass == 0 || t >= 1)) STAGE((sgn + t + 1) & 7, (t+1)&1);

            const float* ar = heT + (ck*32)*76 + jp*20;
            const float* wr = sm + K2_WCH + (t&1)*8192 + nb;
            #pragma unroll 8
            for (int cc = 0; cc < 32; cc++) {
                ulonglong2 a0 = *(const ulonglong2*)(ar);
                ulonglong2 a1 = *(const ulonglong2*)(ar + 4);
                ulonglong2 a2 = *(const ulonglong2*)(ar + 8);
                ulonglong2 a3 = *(const ulonglong2*)(ar + 12);
                float4 w4 = *(const float4*)(wr);
                ull bb0 = bcast2(w4.x), bb1 = bcast2(w4.y);
                ull bb2 = bcast2(w4.z), bb3 = bcast2(w4.w);
                fma2(acc[0][0], a0.x, bb0); fma2(acc[0][1], a0.y, bb0);
                fma2(acc[0][2], a1.x, bb0); fma2(acc[0][3], a1.y, bb0);
                fma2(acc[0][4], a2.x, bb0); fma2(acc[0][5], a2.y, bb0);
                fma2(acc[0][6], a3.x, bb0); fma2(acc[0][7], a3.y, bb0);
                fma2(acc[1][0], a0.x, bb1); fma2(acc[1][1], a0.y, bb1);
                fma2(acc[1][2], a1.x, bb1); fma2(acc[1][3], a1.y, bb1);
                fma2(acc[1][4], a2.x, bb1); fma2(acc[1][5], a2.y, bb1);
                fma2(acc[1][6], a3.x, bb1); fma2(acc[1][7], a3.y, bb1);
                fma2(acc[2][0], a0.x, bb2); fma2(acc[2][1], a0.y, bb2);
                fma2(acc[2][2], a1.x, bb2); fma2(acc[2][3], a1.y, bb2);
                fma2(acc[2][4], a2.x, bb2); fma2(acc[2][5], a2.y, bb2);
                fma2(acc[2][6], a3.x, bb2); fma2(acc[2][7], a3.y, bb2);
                fma2(acc[3][0], a0.x, bb3); fma2(acc[3][1], a0.y, bb3);
                fma2(acc[3][2], a1.x, bb3); fma2(acc[3][3], a1.y, bb3);
                fma2(acc[3][4], a2.x, bb3); fma2(acc[3][5], a2.y, bb3);
                fma2(acc[3][6], a3.x, bb3); fma2(acc[3][7], a3.y, bb3);
                ar += 76; wr += 256;
            }
        }

        #pragma unroll
        for (int p = 0; p < 8; p++) {
            float4 x0 = *(const float4*)&xdnH[(j0 + jp*16 + 2*p)*4];
            float4 x1 = *(const float4*)&xdnH[(j0 + jp*16 + 2*p + 1)*4];
            #pragma unroll
            for (int n = 0; n < 4; n++) {
                float c0, c1; unpack2(acc[n][p], c0, c1);
                float t0 = ftanh(c0), t1 = ftanh(c1);
                cmx[n] += x0.x*t0 + x1.x*t1;
                cmy[n] += x0.y*t0 + x1.y*t1;
                cmz[n] += x0.z*t0 + x1.z*t1;
            }
        }
    }
    g_heE[node*512 + jh*256 + tid] = heE;

    #pragma unroll
    for (int n = 0; n < 4; n++) {
        #pragma unroll
        for (int o = 8; o <= 16; o <<= 1) {
            cmx[n] += __shfl_xor_sync(~0u, cmx[n], o);
            cmy[n] += __shfl_xor_sync(~0u, cmy[n], o);
            cmz[n] += __shfl_xor_sync(~0u, cmz[n], o);
        }
    }
    if (jp == 0) {
        const int base = node*1536 + jh*768;
        #pragma unroll
        for (int n = 0; n < 4; n++) {
            g_cmp[base +       nb + n] = cmx[n];
            g_cmp[base + 256 + nb + n] = cmy[n];
            g_cmp[base + 512 + nb + n] = cmz[n];
        }
    }
}

// ================= K3: phases 5-6 per node =================
__global__ __launch_bounds__(256, 1)
void sake_k3(const float* __restrict__ h, const float* __restrict__ x,
             const float* __restrict__ v,
             const float* __restrict__ Wv_mix,
             const float* __restrict__ Wp1, const float* __restrict__ bp1,
             const float* __restrict__ Wp2, const float* __restrict__ bp2,
             const float* __restrict__ Wn1, const float* __restrict__ bn1,
             const float* __restrict__ Wn2, const float* __restrict__ bn2,
             const float* __restrict__ Wvel1, const float* __restrict__ bvel1,
             const float* __restrict__ Wvel2,
             float* __restrict__ outH, float* __restrict__ outX,
             float* __restrict__ outV) {
    __shared__ __align__(16) float red[40];
    __shared__ float cn[256], part[256], cat[384];
    __shared__ float p1_s[64], hcomb[64], n1_s[64], hn_s[64], hi_s[64];
    const int tid = threadIdx.x;
    const int node = blockIdx.x;

    const float invN = 1.f/256.f;
    const int base = node*1536;
    float csx = (g_cmp[base + tid]       + g_cmp[base + 768 + tid])  * invN;
    float csy = (g_cmp[base + 256 + tid] + g_cmp[base + 1024 + tid]) * invN;
    float csz = (g_cmp[base + 512 + tid] + g_cmp[base + 1280 + tid]) * invN;
    cn[tid] = csx*csx + csy*csy + csz*csz;
    float wv = Wv_mix[tid];
    cat[64 + tid] = g_heE[node*512 + tid] + g_heE[node*512 + 256 + tid];
    if (tid < 64) { float hv = h[node*64 + tid]; cat[tid] = hv; hi_s[tid] = hv; }
    float4 dv4 = block_red4<0>(make_float4(wv*csx, wv*csy, wv*csz, 0.f), tid, red);

    const int g6 = tid >> 6, o6 = tid & 63;
    {   // p1: 256 -> 64
        float a = 0.f;
        const float* wp = Wp1 + g6*64*64 + o6;
        const float* cnp = cn + g6*64;
        #pragma unroll 4
        for (int c = 0; c < 64; c++) a += cnp[c] * wp[c*64];
        part[tid] = a;
    }
    __syncthreads();
    if (tid < 64) {
        float a = bp1[tid] + part[tid] + part[64+tid] + part[128+tid] + part[192+tid];
        p1_s[tid] = siluf(a);
    }
    __syncthreads();
    {   // p2: 64 -> 64
        float a = 0.f;
        const float* wp = Wp2 + g6*16*64 + o6;
        #pragma unroll
        for (int f = 0; f < 16; f++) a += p1_s[g6*16+f] * wp[f*64];
        part[tid] = a;
    }
    __syncthreads();
    if (tid < 64) {
        float a = bp2[tid] + part[tid] + part[64+tid] + part[128+tid] + part[192+tid];
        float hc = siluf(a);
        hcomb[tid] = hc;
        cat[320 + tid] = hc;
    }
    __syncthreads();
    {   // n1: 384 -> 64
        float a = 0.f;
        const float* wp = Wn1 + g6*96*64 + o6;
        const float* cp = cat + g6*96;
        #pragma unroll 4
        for (int r = 0; r < 96; r++) a += cp[r] * wp[r*64];
        part[tid] = a;
    }
    __syncthreads();
    if (tid < 64) {
        float a = bn1[tid] + part[tid] + part[64+tid] + part[128+tid] + part[192+tid];
        n1_s[tid] = siluf(a);
    }
    __syncthreads();
    {   // n2: 64 -> 64
        float a = 0.f;
        const float* wp = Wn2 + g6*16*64 + o6;
        #pragma unroll
        for (int f = 0; f < 16; f++) a += n1_s[g6*16+f] * wp[f*64];
        part[tid] = a;
    }
    __syncthreads();
    if (tid < 64) {
        float a = bn2[tid] + part[tid] + part[64+tid] + part[128+tid] + part[192+tid];
        float hv = hi_s[tid] + siluf(a);
        hn_s[tid] = hv;
        outH[node*64+tid] = hv;
    }
    __syncthreads();
    {   // vel1: 64 -> 64
        float a = 0.f;
        const float* wp = Wvel1 + g6*16*64 + o6;
        #pragma unroll
        for (int f = 0; f < 16; f++) a += hn_s[g6*16+f] * wp[f*64];
        part[tid] = a;
    }
    __syncthreads();
    float vl = 0.f;
    if (tid < 64) {
        float a = bvel1[tid] + part[tid] + part[64+tid] + part[128+tid] + part[192+tid];
        vl = siluf(a) * Wvel2[tid];
    }
    float4 vs = block_red4<0>(make_float4(vl, 0.f, 0.f, 0.f), tid, red);
    if (tid == 0) {
        float scale = 2.f * sigm(vs.x);
        float dvv[3] = {dv4.x, dv4.y, dv4.z};
        #pragma unroll
        for (int t = 0; t < 3; t++) {
            float vn = dvv[t] + scale * v[node*3+t];
            outV[node*3+t] = vn;
            outX[node*3+t] = x[node*3+t] + vn;
        }
    }
}

// ---------------- launch ----------------
extern "C" void kernel_launch(void* const* d_in, const int* in_sizes, int n_in,
                              void* d_out, int out_size) {
    const float* h      = (const float*)d_in[0];
    const float* x      = (const float*)d_in[1];
    const float* v      = (const float*)d_in[2];
    const float* means  = (const float*)d_in[3];
    const float* betas  = (const float*)d_in[4];
    const float* W_in   = (const float*)d_in[5];
    const float* b_in   = (const float*)d_in[6];
    const float* W_o1   = (const float*)d_in[7];
    const float* b_o1   = (const float*)d_in[8];
    const float* W_o2   = (const float*)d_in[9];
    const float* b_o2   = (const float*)d_in[10];
    const float* Ws     = (const float*)d_in[11];
    const float* bs     = (const float*)d_in[12];
    const float* lgam   = (const float*)d_in[13];
    const float* Wx     = (const float*)d_in[14];
    const float* Wp1    = (const float*)d_in[15];
    const float* bp1    = (const float*)d_in[16];
    const float* Wp2    = (const float*)d_in[17];
    const float* bp2    = (const float*)d_in[18];
    const float* Wn1    = (const float*)d_in[19];
    const float* bn1    = (const float*)d_in[20];
    const float* Wn2    = (const float*)d_in[21];
    const float* bn2    = (const float*)d_in[22];
    const float* Wv_mix = (const float*)d_in[23];
    const float* Wvel1  = (const float*)d_in[24];
    const float* bvel1  = (const float*)d_in[25];
    const float* Wvel2  = (const float*)d_in[26];

    float* out  = (float*)d_out;
    float* outH = out;
    float* outX = out + BB*NN*FF;
    float* outV = outX + BB*NN*3;

    cudaFuncSetAttribute(sake_k1, cudaFuncAttributeMaxDynamicSharedMemorySize, K1_BYTES);
    cudaFuncSetAttribute(sake_k2, cudaFuncAttributeMaxDynamicSharedMemorySize, K2_BYTES);

    prenode_kernel<<<BB*NN, 128>>>(h, W_in, W_o1);
    sake_k1<<<BB*NN, 256, K1_BYTES>>>(x, means, betas, b_in, W_o1, b_o1, b_o2, W_o2,
                                      Ws, bs, lgam);
    sake_k2<<<BB*NN*2, 256, K2_BYTES>>>(Wx);
    sake_k3<<<BB*NN, 256>>>(h, x, v, Wv_mix, Wp1, bp1, Wp2, bp2,
                            Wn1, bn1, Wn2, bn2, Wvel1, bvel1, Wvel2,
                            outH, outX, outV);
}